// round 1
// baseline (speedup 1.0000x reference)
#include <cuda_runtime.h>

// MoE experts: two grouped GEMMs.
//   up   = hiddens[T,H] @ w1[e,H,I]  -> [T,I]
//   down = up[T,I]      @ w2[e,I,H]  -> [T,H]
// E=8, H=1024, I=4096, T=8192, equal segments of 1024 tokens per expert.

#define NE 8
#define TT 8192
#define HH 1024
#define II 4096

// scratch for the intermediate activation (allocation-free rule: __device__ global)
__device__ float g_up[(size_t)TT * (size_t)II];

typedef unsigned long long u64;

__device__ __forceinline__ void ffma2(u64 &d, u64 a, u64 b) {
    // packed f32x2 FMA: d.lo += a.lo*b.lo ; d.hi += a.hi*b.hi
    asm("fma.rn.f32x2 %0, %1, %2, %0;" : "+l"(d) : "l"(a), "l"(b));
}

__device__ __forceinline__ u64 bcast2(float x) {
    u64 r;
    unsigned u = __float_as_uint(x);
    asm("mov.b64 %0, {%1, %1};" : "=l"(r) : "r"(u));
    return r;
}

__device__ __forceinline__ float2 unpack2(u64 v) {
    float2 f;
    asm("mov.b64 {%0, %1}, %2;" : "=f"(f.x), "=f"(f.y) : "l"(v));
    return f;
}

// C[row0:row0+128, n0:n0+128] = A[rows, :K] @ W[expert(row0), :K, n0:n0+128]
// A: [T, K] row-major, W: [E, K, N] row-major, C: [T, N] row-major.
__global__ __launch_bounds__(256, 2)
void gemm_moe(const float* __restrict__ A, const float* __restrict__ W,
              const int* __restrict__ bsz, float* __restrict__ C,
              int K, int N)
{
    __shared__ float As[16][128];   // transposed A tile: As[k][m]
    __shared__ float Bs[16][128];   // Bs[k][n]

    const int tid  = threadIdx.x;
    const int row0 = blockIdx.y * 128;
    const int n0   = blockIdx.x * 128;

    // expert owning this row tile: largest e with cumsum_before(e) <= row0
    int cum = 0, e = 0;
#pragma unroll
    for (int i = 0; i < NE; i++) {
        if (row0 >= cum) e = i;
        cum += bsz[i];
    }
    const float* Wb = W + (size_t)e * (size_t)K * (size_t)N;

    // ---- global-load prefetch (tile 0) ----
    float4 pa[2], pb[2];
#pragma unroll
    for (int l = 0; l < 2; l++) {
        int idx = tid + l * 256;
        int ar = idx >> 2, kq = idx & 3;            // A: 128 rows x 4 float4 (k)
        pa[l] = *(const float4*)&A[(size_t)(row0 + ar) * K + kq * 4];
        int br = idx >> 5, bc = idx & 31;           // B: 16 rows (k) x 32 float4 (n)
        pb[l] = *(const float4*)&Wb[(size_t)br * N + n0 + bc * 4];
    }

    const int tx = tid & 15;   // n-tile index (8 cols each)
    const int ty = tid >> 4;   // m-tile index (8 rows each)

    // accumulators: 4 m-pairs x 8 n, each a packed f32x2 along M
    u64 acc[4][8];
#pragma unroll
    for (int i = 0; i < 4; i++)
#pragma unroll
        for (int j = 0; j < 8; j++) acc[i][j] = 0ull;

    for (int kt = 0; kt < K; kt += 16) {
        // commit prefetched tile to shared
#pragma unroll
        for (int l = 0; l < 2; l++) {
            int idx = tid + l * 256;
            int ar = idx >> 2, kq = idx & 3;
            As[kq * 4 + 0][ar] = pa[l].x;
            As[kq * 4 + 1][ar] = pa[l].y;
            As[kq * 4 + 2][ar] = pa[l].z;
            As[kq * 4 + 3][ar] = pa[l].w;
            int br = idx >> 5, bc = idx & 31;
            *(float4*)&Bs[br][bc * 4] = pb[l];
        }
        __syncthreads();

        // prefetch next tile while computing this one
        if (kt + 16 < K) {
#pragma unroll
            for (int l = 0; l < 2; l++) {
                int idx = tid + l * 256;
                int ar = idx >> 2, kq = idx & 3;
                pa[l] = *(const float4*)&A[(size_t)(row0 + ar) * K + (kt + 16) + kq * 4];
                int br = idx >> 5, bc = idx & 31;
                pb[l] = *(const float4*)&Wb[(size_t)(kt + 16 + br) * N + n0 + bc * 4];
            }
        }

#pragma unroll
        for (int kk = 0; kk < 16; kk++) {
            // A pairs along m: contiguous in As[kk] -> direct 64-bit loads
            const u64* ap = (const u64*)&As[kk][ty * 8];
            u64 a0 = ap[0], a1 = ap[1], a2 = ap[2], a3 = ap[3];

            float4 b04 = *(const float4*)&Bs[kk][tx * 8];
            float4 b14 = *(const float4*)&Bs[kk][tx * 8 + 4];
            u64 bb[8];
            bb[0] = bcast2(b04.x); bb[1] = bcast2(b04.y);
            bb[2] = bcast2(b04.z); bb[3] = bcast2(b04.w);
            bb[4] = bcast2(b14.x); bb[5] = bcast2(b14.y);
            bb[6] = bcast2(b14.z); bb[7] = bcast2(b14.w);

#pragma unroll
            for (int j = 0; j < 8; j++) {
                ffma2(acc[0][j], a0, bb[j]);
                ffma2(acc[1][j], a1, bb[j]);
                ffma2(acc[2][j], a2, bb[j]);
                ffma2(acc[3][j], a3, bb[j]);
            }
        }
        __syncthreads();
    }

    // ---- epilogue: unpack pairs, vectorized stores ----
#pragma unroll
    for (int i2 = 0; i2 < 4; i2++) {
        float lo[8], hi[8];
#pragma unroll
        for (int j = 0; j < 8; j++) {
            float2 v = unpack2(acc[i2][j]);
            lo[j] = v.x; hi[j] = v.y;
        }
        int m = row0 + ty * 8 + i2 * 2;
        float* c0 = &C[(size_t)m * N + n0 + tx * 8];
        float* c1 = c0 + N;
        *(float4*)(c0)     = make_float4(lo[0], lo[1], lo[2], lo[3]);
        *((float4*)c0 + 1) = make_float4(lo[4], lo[5], lo[6], lo[7]);
        *(float4*)(c1)     = make_float4(hi[0], hi[1], hi[2], hi[3]);
        *((float4*)c1 + 1) = make_float4(hi[4], hi[5], hi[6], hi[7]);
    }
}

extern "C" void kernel_launch(void* const* d_in, const int* in_sizes, int n_in,
                              void* d_out, int out_size)
{
    const float* hiddens = (const float*)d_in[0];
    const int*   bsz     = (const int*)d_in[1];
    const float* w1      = (const float*)d_in[2];
    const float* w2      = (const float*)d_in[3];
    float*       out     = (float*)d_out;

    float* up = nullptr;
    cudaGetSymbolAddress((void**)&up, g_up);

    dim3 blk(256);
    // up = hiddens @ w1[e] : K=H=1024, N=I=4096
    gemm_moe<<<dim3(II / 128, TT / 128), blk>>>(hiddens, w1, bsz, up, HH, II);
    // down = up @ w2[e]    : K=I=4096, N=H=1024
    gemm_moe<<<dim3(HH / 128, TT / 128), blk>>>(up, w2, bsz, out, II, HH);
}

// round 5
// speedup vs baseline: 1.8584x; 1.8584x over previous
#include <cuda_runtime.h>
#include <cuda_bf16.h>

#define NE 8
#define TT 8192
#define HH 1024
#define II 4096

typedef unsigned int u32;

__device__ float g_up[(size_t)TT * (size_t)II];

// ---- smem layout (in bf16 halves), per stage ----
// Ahi [128][24], Alo [128][24], Bhi [16][136], Blo [16][136]
#define A_ROW 24
#define B_ROW 136
#define OFF_AHI 0
#define OFF_ALO (128 * A_ROW)              // 3072
#define OFF_BHI (2 * 128 * A_ROW)          // 6144
#define OFF_BLO (OFF_BHI + 16 * B_ROW)     // 8320
#define STAGE_H (OFF_BHI + 2 * 16 * B_ROW) // 10496 halves = 20992 B
#define SMEM_BYTES (2 * STAGE_H * 2)       // 41984 B (double buffer)

static __device__ __forceinline__ u32 smem_u32(const void* p) {
    u32 a;
    asm("{ .reg .u64 t; cvta.to.shared.u64 t, %1; cvt.u32.u64 %0, t; }" : "=r"(a) : "l"(p));
    return a;
}

#define LDSM4(r, addr)                                                        \
    asm volatile("ldmatrix.sync.aligned.m8n8.x4.shared.b16 {%0,%1,%2,%3}, [%4];" \
                 : "=r"((r)[0]), "=r"((r)[1]), "=r"((r)[2]), "=r"((r)[3])     \
                 : "r"(addr))

#define LDSM4T(r, addr)                                                       \
    asm volatile("ldmatrix.sync.aligned.m8n8.x4.trans.shared.b16 {%0,%1,%2,%3}, [%4];" \
                 : "=r"((r)[0]), "=r"((r)[1]), "=r"((r)[2]), "=r"((r)[3])     \
                 : "r"(addr))

#define MMA16816(d, a, b0, b1)                                                \
    asm volatile("mma.sync.aligned.m16n8k16.row.col.f32.bf16.bf16.f32 "       \
                 "{%0,%1,%2,%3},{%4,%5,%6,%7},{%8,%9},{%0,%1,%2,%3};"         \
                 : "+f"((d)[0]), "+f"((d)[1]), "+f"((d)[2]), "+f"((d)[3])     \
                 : "r"((a)[0]), "r"((a)[1]), "r"((a)[2]), "r"((a)[3]),        \
                   "r"(b0), "r"(b1))

static __device__ __forceinline__ void cvt_hilo(float x, float y, u32& h, u32& l) {
    __nv_bfloat162 hb = __float22bfloat162_rn(make_float2(x, y));
    float2 hf = __bfloat1622float2(hb);
    __nv_bfloat162 lb = __float22bfloat162_rn(make_float2(x - hf.x, y - hf.y));
    h = *(u32*)&hb;
    l = *(u32*)&lb;
}

// C[row0:+128, n0:+128] = A[rows,:K] @ W[e,:K,n0:+128]
// A:[T,K] row-major, W:[E,K,N] row-major, C:[T,N] row-major
__global__ __launch_bounds__(256, 2)
void gemm_moe_hmma(const float* __restrict__ A, const float* __restrict__ W,
                   const int* __restrict__ bsz, float* __restrict__ C,
                   int K, int N)
{
    extern __shared__ __nv_bfloat16 sm[];
    const u32 sbase = smem_u32(sm);
    const int tid = threadIdx.x;
    const int lane = tid & 31;
    const int wid = tid >> 5;
    const int warp_m = wid & 3;   // 4 warps along m (32 rows each)
    const int warp_n = wid >> 2;  // 2 warps along n (64 cols each)
    const int row0 = blockIdx.y * 128;
    const int n0 = blockIdx.x * 128;

    // expert owning this 128-row tile (segments are multiples of 1024 rows)
    int cum = 0, e = 0;
#pragma unroll
    for (int i = 0; i < NE; i++) { if (row0 >= cum) e = i; cum += bsz[i]; }
    const float* Wb = W + (size_t)e * (size_t)K * (size_t)N;

    // ---- ldmatrix per-lane byte offsets (stage-relative) ----
    // A frag (m16k16) at m0: lanes 0-15 -> rows m0+(lane&15) col 0; 16-31 -> col 8
    const int a_r = lane & 15, a_c = (lane >> 4) * 8;
    u32 aoff[2];
#pragma unroll
    for (int mf = 0; mf < 2; mf++)
        aoff[mf] = (u32)(((warp_m * 32 + mf * 16 + a_r) * A_ROW + a_c) * 2);
    // B frags (.trans) for n-pair at nb: lane -> row k=(lane&7)+8*((lane>>3)&1),
    // col n = nb + 8*(lane>>4)
    const int b_k = (lane & 7) + 8 * ((lane >> 3) & 1);
    const int b_n = 8 * (lane >> 4);
    u32 boff[4];
#pragma unroll
    for (int j = 0; j < 4; j++)
        boff[j] = (u32)((OFF_BHI + b_k * B_ROW + warp_n * 64 + j * 16 + b_n) * 2);

    float acc[2][8][4];
#pragma unroll
    for (int mf = 0; mf < 2; mf++)
#pragma unroll
        for (int nf = 0; nf < 8; nf++)
#pragma unroll
            for (int v = 0; v < 4; v++) acc[mf][nf][v] = 0.0f;

    const int NS = K >> 4;  // 16 fp32 K per stage
    float4 pa[2], pb[2];

    // prefetch stage 0
#pragma unroll
    for (int i = 0; i < 2; i++) {
        int f = tid + i * 256;
        int m = f >> 2, q = f & 3;
        pa[i] = *(const float4*)(A + (size_t)(row0 + m) * K + q * 4);
        int k = f >> 5, c = f & 31;
        pb[i] = *(const float4*)(Wb + (size_t)k * N + n0 + c * 4);
    }

    for (int s = 0; s < NS; s++) {
        const int b = s & 1;
        __nv_bfloat16* base = sm + b * STAGE_H;

        // ---- convert + store current stage ----
#pragma unroll
        for (int i = 0; i < 2; i++) {
            int f = tid + i * 256;
            int m = f >> 2, q = f & 3;
            u32 h0, l0, h1, l1;
            cvt_hilo(pa[i].x, pa[i].y, h0, l0);
            cvt_hilo(pa[i].z, pa[i].w, h1, l1);
            u32* ah = (u32*)(base + OFF_AHI + m * A_ROW + q * 4);
            u32* al = (u32*)(base + OFF_ALO + m * A_ROW + q * 4);
            ah[0] = h0; ah[1] = h1;
            al[0] = l0; al[1] = l1;
            int k = f >> 5, c = f & 31;
            cvt_hilo(pb[i].x, pb[i].y, h0, l0);
            cvt_hilo(pb[i].z, pb[i].w, h1, l1);
            u32* bh = (u32*)(base + OFF_BHI + k * B_ROW + c * 4);
            u32* bl = (u32*)(base + OFF_BLO + k * B_ROW + c * 4);
            bh[0] = h0; bh[1] = h1;
            bl[0] = l0; bl[1] = l1;
        }
        __syncthreads();

        // ---- prefetch next stage (overlaps with MMA below) ----
        if (s + 1 < NS) {
            const int kt = (s + 1) << 4;
#pragma unroll
            for (int i = 0; i < 2; i++) {
                int f = tid + i * 256;
                int m = f >> 2, q = f & 3;
                pa[i] = *(const float4*)(A + (size_t)(row0 + m) * K + kt + q * 4);
                int k = f >> 5, c = f & 31;
                pb[i] = *(const float4*)(Wb + (size_t)(kt + k) * N + n0 + c * 4);
            }
        }

        // ---- MMA: AhiBhi + AloBhi + AhiBlo ----
        const u32 stb = sbase + (u32)(b * STAGE_H * 2);
        u32 ah[2][4], al[2][4], bf[4][4];
#pragma unroll
        for (int mf = 0; mf < 2; mf++) LDSM4(ah[mf], stb + aoff[mf]);
#pragma unroll
        for (int mf = 0; mf < 2; mf++) LDSM4(al[mf], stb + aoff[mf] + (u32)(OFF_ALO * 2));
#pragma unroll
        for (int j = 0; j < 4; j++) LDSM4T(bf[j], stb + boff[j]);   // B hi
#pragma unroll
        for (int mf = 0; mf < 2; mf++)
#pragma unroll
            for (int j = 0; j < 4; j++) {
                MMA16816(acc[mf][2 * j],     ah[mf], bf[j][0], bf[j][1]);
                MMA16816(acc[mf][2 * j + 1], ah[mf], bf[j][2], bf[j][3]);
            }
#pragma unroll
        for (int mf = 0; mf < 2; mf++)
#pragma unroll
            for (int j = 0; j < 4; j++) {
                MMA16816(acc[mf][2 * j],     al[mf], bf[j][0], bf[j][1]);
                MMA16816(acc[mf][2 * j + 1], al[mf], bf[j][2], bf[j][3]);
            }
#pragma unroll
        for (int j = 0; j < 4; j++) LDSM4T(bf[j], stb + boff[j] + (u32)((OFF_BLO - OFF_BHI) * 2)); // B lo
#pragma unroll
        for (int mf = 0; mf < 2; mf++)
#pragma unroll
            for (int j = 0; j < 4; j++) {
                MMA16816(acc[mf][2 * j],     ah[mf], bf[j][0], bf[j][1]);
                MMA16816(acc[mf][2 * j + 1], ah[mf], bf[j][2], bf[j][3]);
            }
        // no trailing sync needed: double buffer + the sync above protect reuse
    }

    // ---- epilogue ----
#pragma unroll
    for (int mf = 0; mf < 2; mf++)
#pragma unroll
        for (int nf = 0; nf < 8; nf++) {
            int r = row0 + warp_m * 32 + mf * 16 + (lane >> 2);
            int c = n0 + warp_n * 64 + nf * 8 + (lane & 3) * 2;
            *(float2*)(C + (size_t)r * N + c) =
                make_float2(acc[mf][nf][0], acc[mf][nf][1]);
            *(float2*)(C + (size_t)(r + 8) * N + c) =
                make_float2(acc[mf][nf][2], acc[mf][nf][3]);
        }
}

extern "C" void kernel_launch(void* const* d_in, const int* in_sizes, int n_in,
                              void* d_out, int out_size)
{
    const float* hiddens = (const float*)d_in[0];
    const int*   bsz     = (const int*)d_in[1];
    const float* w1      = (const float*)d_in[2];
    const float* w2      = (const float*)d_in[3];
    float*       out     = (float*)d_out;

    float* up = nullptr;
    cudaGetSymbolAddress((void**)&up, g_up);

    // up = hiddens @ w1[e] : K=H=1024, N=I=4096
    gemm_moe_hmma<<<dim3(II / 128, TT / 128), 256, SMEM_BYTES>>>(hiddens, w1, bsz, up, HH, II);
    // down = up @ w2[e]    : K=I=4096, N=H=1024
    gemm_moe_hmma<<<dim3(HH / 128, TT / 128), 256, SMEM_BYTES>>>(up, w2, bsz, out, II, HH);
}

// round 6
// speedup vs baseline: 2.6216x; 1.4107x over previous
#include <cuda_runtime.h>
#include <cuda_bf16.h>

#define NE 8
#define TT 8192
#define HH 1024
#define II 4096

typedef unsigned int u32;

// ---- precomputed bf16 hi/lo planes (allocation-free: __device__ globals) ----
__device__ __nv_bfloat16 g_xh[(size_t)TT * HH],  g_xl[(size_t)TT * HH];
__device__ __nv_bfloat16 g_w1h[(size_t)NE * HH * II], g_w1l[(size_t)NE * HH * II];
__device__ __nv_bfloat16 g_w2h[(size_t)NE * II * HH], g_w2l[(size_t)NE * II * HH];
__device__ __nv_bfloat16 g_uph[(size_t)TT * II], g_upl[(size_t)TT * II];

// ---- smem stage layout (bf16 halves) ----
// Ahi [128][24], Alo [128][24], Bhi [16][136], Blo [16][136]
#define A_ROW 24
#define B_ROW 136
#define OFF_ALO (128 * A_ROW)                 // 3072
#define OFF_BHI (2 * 128 * A_ROW)             // 6144
#define OFF_BLO (OFF_BHI + 16 * B_ROW)        // 8320
#define STAGE_H (OFF_BHI + 2 * 16 * B_ROW)    // 10496 halves
#define STAGE_B (STAGE_H * 2)                 // 20992 bytes
#define NSTAGE  4
#define SMEM_BYTES (NSTAGE * STAGE_B)         // 83968

static __device__ __forceinline__ u32 smem_u32(const void* p) {
    u32 a;
    asm("{ .reg .u64 t; cvta.to.shared.u64 t, %1; cvt.u32.u64 %0, t; }" : "=r"(a) : "l"(p));
    return a;
}

#define CP16(dst, src) \
    asm volatile("cp.async.cg.shared.global [%0], [%1], 16;" :: "r"(dst), "l"(src))
#define CP_COMMIT() asm volatile("cp.async.commit_group;" ::: "memory")
#define CP_WAIT2()  asm volatile("cp.async.wait_group 2;" ::: "memory")

#define LDSM4(r, addr)                                                        \
    asm volatile("ldmatrix.sync.aligned.m8n8.x4.shared.b16 {%0,%1,%2,%3}, [%4];" \
                 : "=r"((r)[0]), "=r"((r)[1]), "=r"((r)[2]), "=r"((r)[3])     \
                 : "r"(addr))

#define LDSM4T(r, addr)                                                       \
    asm volatile("ldmatrix.sync.aligned.m8n8.x4.trans.shared.b16 {%0,%1,%2,%3}, [%4];" \
                 : "=r"((r)[0]), "=r"((r)[1]), "=r"((r)[2]), "=r"((r)[3])     \
                 : "r"(addr))

#define MMA16816(d, a, b0, b1)                                                \
    asm volatile("mma.sync.aligned.m16n8k16.row.col.f32.bf16.bf16.f32 "       \
                 "{%0,%1,%2,%3},{%4,%5,%6,%7},{%8,%9},{%0,%1,%2,%3};"         \
                 : "+f"((d)[0]), "+f"((d)[1]), "+f"((d)[2]), "+f"((d)[3])     \
                 : "r"((a)[0]), "r"((a)[1]), "r"((a)[2]), "r"((a)[3]),        \
                   "r"(b0), "r"(b1))

static __device__ __forceinline__ void cvt_hilo(float x, float y, u32& h, u32& l) {
    __nv_bfloat162 hb = __float22bfloat162_rn(make_float2(x, y));
    float2 hf = __bfloat1622float2(hb);
    __nv_bfloat162 lb = __float22bfloat162_rn(make_float2(x - hf.x, y - hf.y));
    h = *(u32*)&hb;
    l = *(u32*)&lb;
}

// ---- split fp32 -> (hi, lo) bf16 planes ----
__global__ __launch_bounds__(256)
void cvt_split_k(const float4* __restrict__ src, uint2* __restrict__ h,
                 uint2* __restrict__ l, int n4)
{
    int i = blockIdx.x * 256 + threadIdx.x;
    if (i < n4) {
        float4 v = src[i];
        u32 h0, l0, h1, l1;
        cvt_hilo(v.x, v.y, h0, l0);
        cvt_hilo(v.z, v.w, h1, l1);
        h[i] = make_uint2(h0, h1);
        l[i] = make_uint2(l0, l1);
    }
}

// C[row0:+128, n0:+128] = A[rows,:K] @ W[e,:K,n0:+128], all operands bf16 hi/lo planes.
// EPI=0: write fp32 C. EPI=1: write hi/lo bf16 planes Ch/Cl.
template <int EPI>
__global__ __launch_bounds__(256, 2)
void gemm_moe_async(const __nv_bfloat16* __restrict__ Ah, const __nv_bfloat16* __restrict__ Al,
                    const __nv_bfloat16* __restrict__ Wh, const __nv_bfloat16* __restrict__ Wl,
                    const int* __restrict__ bsz, float* __restrict__ C,
                    __nv_bfloat16* __restrict__ Ch, __nv_bfloat16* __restrict__ Cl,
                    int K, int N)
{
    extern __shared__ __nv_bfloat16 sm[];
    const u32 sbase = smem_u32(sm);
    const int tid = threadIdx.x;
    const int lane = tid & 31;
    const int wid = tid >> 5;
    const int warp_m = wid & 3;
    const int warp_n = wid >> 2;
    const int row0 = blockIdx.y * 128;
    const int n0 = blockIdx.x * 128;

    int cum = 0, e = 0;
#pragma unroll
    for (int i = 0; i < NE; i++) { if (row0 >= cum) e = i; cum += bsz[i]; }
    const size_t woff = (size_t)e * (size_t)K * (size_t)N;

    // ---- per-thread cp.async source/dest mapping ----
    const int ar = tid >> 1, ac = (tid & 1) * 8;       // A: 128 rows x 2 chunks
    const int bk = tid >> 4, bc = (tid & 15) * 8;      // B: 16 rows x 16 chunks
    const __nv_bfloat16* sAh = Ah + (size_t)(row0 + ar) * K + ac;
    const __nv_bfloat16* sAl = Al + (size_t)(row0 + ar) * K + ac;
    const __nv_bfloat16* sBh = Wh + woff + (size_t)bk * N + n0 + bc;
    const __nv_bfloat16* sBl = Wl + woff + (size_t)bk * N + n0 + bc;
    const u32 dA = (u32)((ar * A_ROW + ac) * 2);
    const u32 dB = (u32)((bk * B_ROW + bc) * 2);

    // ---- ldmatrix per-lane byte offsets (stage-relative) ----
    const int a_r = lane & 15, a_c = (lane >> 4) * 8;
    u32 aoff[2];
#pragma unroll
    for (int mf = 0; mf < 2; mf++)
        aoff[mf] = (u32)(((warp_m * 32 + mf * 16 + a_r) * A_ROW + a_c) * 2);
    const int b_k = (lane & 7) + 8 * ((lane >> 3) & 1);
    const int b_n = 8 * (lane >> 4);
    u32 boff[4];
#pragma unroll
    for (int j = 0; j < 4; j++)
        boff[j] = (u32)((OFF_BHI + b_k * B_ROW + warp_n * 64 + j * 16 + b_n) * 2);

    float acc[2][8][4];
#pragma unroll
    for (int mf = 0; mf < 2; mf++)
#pragma unroll
        for (int nf = 0; nf < 8; nf++)
#pragma unroll
            for (int v = 0; v < 4; v++) acc[mf][nf][v] = 0.0f;

    const int NS = K >> 4;

    // ---- prologue: fill stages 0..2 ----
#pragma unroll
    for (int p = 0; p < NSTAGE - 1; p++) {
        const int kt = p << 4;
        const u32 st = sbase + (u32)(p * STAGE_B);
        CP16(st + dA, sAh + kt);
        CP16(st + OFF_ALO * 2 + dA, sAl + kt);
        CP16(st + OFF_BHI * 2 + dB, sBh + (size_t)kt * N);
        CP16(st + OFF_BLO * 2 + dB, sBl + (size_t)kt * N);
        CP_COMMIT();
    }

    for (int s = 0; s < NS; s++) {
        CP_WAIT2();
        __syncthreads();

        if (s + NSTAGE - 1 < NS) {
            const int kt = (s + NSTAGE - 1) << 4;
            const u32 st = sbase + (u32)(((s + NSTAGE - 1) & (NSTAGE - 1)) * STAGE_B);
            CP16(st + dA, sAh + kt);
            CP16(st + OFF_ALO * 2 + dA, sAl + kt);
            CP16(st + OFF_BHI * 2 + dB, sBh + (size_t)kt * N);
            CP16(st + OFF_BLO * 2 + dB, sBl + (size_t)kt * N);
        }
        CP_COMMIT();   // always commit (empty groups keep wait_group accounting sound)

        // ---- MMA: AhiBhi + AloBhi + AhiBlo ----
        const u32 stb = sbase + (u32)((s & (NSTAGE - 1)) * STAGE_B);
        u32 ah[2][4], al[2][4], bf[4][4];
#pragma unroll
        for (int mf = 0; mf < 2; mf++) LDSM4(ah[mf], stb + aoff[mf]);
#pragma unroll
        for (int mf = 0; mf < 2; mf++) LDSM4(al[mf], stb + aoff[mf] + (u32)(OFF_ALO * 2));
#pragma unroll
        for (int j = 0; j < 4; j++) LDSM4T(bf[j], stb + boff[j]);   // B hi
#pragma unroll
        for (int mf = 0; mf < 2; mf++)
#pragma unroll
            for (int j = 0; j < 4; j++) {
                MMA16816(acc[mf][2 * j],     ah[mf], bf[j][0], bf[j][1]);
                MMA16816(acc[mf][2 * j + 1], ah[mf], bf[j][2], bf[j][3]);
            }
#pragma unroll
        for (int mf = 0; mf < 2; mf++)
#pragma unroll
            for (int j = 0; j < 4; j++) {
                MMA16816(acc[mf][2 * j],     al[mf], bf[j][0], bf[j][1]);
                MMA16816(acc[mf][2 * j + 1], al[mf], bf[j][2], bf[j][3]);
            }
#pragma unroll
        for (int j = 0; j < 4; j++) LDSM4T(bf[j], stb + boff[j] + (u32)((OFF_BLO - OFF_BHI) * 2));
#pragma unroll
        for (int mf = 0; mf < 2; mf++)
#pragma unroll
            for (int j = 0; j < 4; j++) {
                MMA16816(acc[mf][2 * j],     ah[mf], bf[j][0], bf[j][1]);
                MMA16816(acc[mf][2 * j + 1], ah[mf], bf[j][2], bf[j][3]);
            }
    }

    // ---- epilogue ----
#pragma unroll
    for (int mf = 0; mf < 2; mf++)
#pragma unroll
        for (int nf = 0; nf < 8; nf++) {
            int r = row0 + warp_m * 32 + mf * 16 + (lane >> 2);
            int c = n0 + warp_n * 64 + nf * 8 + (lane & 3) * 2;
            if (EPI == 0) {
                *(float2*)(C + (size_t)r * N + c) =
                    make_float2(acc[mf][nf][0], acc[mf][nf][1]);
                *(float2*)(C + (size_t)(r + 8) * N + c) =
                    make_float2(acc[mf][nf][2], acc[mf][nf][3]);
            } else {
                u32 h, l;
                cvt_hilo(acc[mf][nf][0], acc[mf][nf][1], h, l);
                *(u32*)(Ch + (size_t)r * N + c) = h;
                *(u32*)(Cl + (size_t)r * N + c) = l;
                cvt_hilo(acc[mf][nf][2], acc[mf][nf][3], h, l);
                *(u32*)(Ch + (size_t)(r + 8) * N + c) = h;
                *(u32*)(Cl + (size_t)(r + 8) * N + c) = l;
            }
        }
}

extern "C" void kernel_launch(void* const* d_in, const int* in_sizes, int n_in,
                              void* d_out, int out_size)
{
    const float* hiddens = (const float*)d_in[0];
    const int*   bsz     = (const int*)d_in[1];
    const float* w1      = (const float*)d_in[2];
    const float* w2      = (const float*)d_in[3];
    float*       out     = (float*)d_out;

    __nv_bfloat16 *xh, *xl, *w1h, *w1l, *w2h, *w2l, *uph, *upl;
    cudaGetSymbolAddress((void**)&xh, g_xh);   cudaGetSymbolAddress((void**)&xl, g_xl);
    cudaGetSymbolAddress((void**)&w1h, g_w1h); cudaGetSymbolAddress((void**)&w1l, g_w1l);
    cudaGetSymbolAddress((void**)&w2h, g_w2h); cudaGetSymbolAddress((void**)&w2l, g_w2l);
    cudaGetSymbolAddress((void**)&uph, g_uph); cudaGetSymbolAddress((void**)&upl, g_upl);

    cudaFuncSetAttribute(gemm_moe_async<0>, cudaFuncAttributeMaxDynamicSharedMemorySize, SMEM_BYTES);
    cudaFuncSetAttribute(gemm_moe_async<1>, cudaFuncAttributeMaxDynamicSharedMemorySize, SMEM_BYTES);

    // split conversions
    {
        int n4 = (TT * HH) / 4;
        cvt_split_k<<<(n4 + 255) / 256, 256>>>((const float4*)hiddens, (uint2*)xh, (uint2*)xl, n4);
    }
    {
        int n4 = (NE * HH * II) / 4;
        cvt_split_k<<<(n4 + 255) / 256, 256>>>((const float4*)w1, (uint2*)w1h, (uint2*)w1l, n4);
        cvt_split_k<<<(n4 + 255) / 256, 256>>>((const float4*)w2, (uint2*)w2h, (uint2*)w2l, n4);
    }

    // up = hiddens @ w1[e] : K=1024, N=4096 ; writes hi/lo planes
    gemm_moe_async<1><<<dim3(II / 128, TT / 128), 256, SMEM_BYTES>>>(
        xh, xl, w1h, w1l, bsz, nullptr, uph, upl, HH, II);
    // down = up @ w2[e] : K=4096, N=1024 ; writes fp32
    gemm_moe_async<0><<<dim3(HH / 128, TT / 128), 256, SMEM_BYTES>>>(
        uph, upl, w2h, w2l, bsz, out, nullptr, nullptr, II, HH);
}

// round 7
// speedup vs baseline: 2.6661x; 1.0170x over previous
#include <cuda_runtime.h>
#include <cuda_bf16.h>

#define NE 8
#define TT 8192
#define HH 1024
#define II 4096

typedef unsigned int u32;

// ---- precomputed bf16 hi/lo planes ----
__device__ __nv_bfloat16 g_xh[(size_t)TT * HH],  g_xl[(size_t)TT * HH];
__device__ __nv_bfloat16 g_w1h[(size_t)NE * HH * II], g_w1l[(size_t)NE * HH * II];
__device__ __nv_bfloat16 g_w2h[(size_t)NE * II * HH], g_w2l[(size_t)NE * II * HH];
__device__ __nv_bfloat16 g_uph[(size_t)TT * II], g_upl[(size_t)TT * II];

// ---- smem stage layout (bf16 halves), BK = 32 fp32-k per stage ----
// Ahi [128][40], Alo [128][40], Bhi [32][136], Blo [32][136]
#define A_ROW 40
#define B_ROW 136
#define OFF_ALO (128 * A_ROW)                  // 5120
#define OFF_BHI (2 * 128 * A_ROW)              // 10240
#define OFF_BLO (OFF_BHI + 32 * B_ROW)         // 14592
#define STAGE_H (OFF_BHI + 2 * 32 * B_ROW)     // 18944 halves
#define STAGE_B (STAGE_H * 2)                  // 37888 bytes
#define NSTAGE  3
#define SMEM_BYTES (NSTAGE * STAGE_B)          // 113664

static __device__ __forceinline__ u32 smem_u32(const void* p) {
    u32 a;
    asm("{ .reg .u64 t; cvta.to.shared.u64 t, %1; cvt.u32.u64 %0, t; }" : "=r"(a) : "l"(p));
    return a;
}

#define CP16(dst, src) \
    asm volatile("cp.async.cg.shared.global [%0], [%1], 16;" :: "r"(dst), "l"(src))
#define CP_COMMIT() asm volatile("cp.async.commit_group;" ::: "memory")
#define CP_WAIT1()  asm volatile("cp.async.wait_group 1;" ::: "memory")

#define LDSM4(r, addr)                                                        \
    asm volatile("ldmatrix.sync.aligned.m8n8.x4.shared.b16 {%0,%1,%2,%3}, [%4];" \
                 : "=r"((r)[0]), "=r"((r)[1]), "=r"((r)[2]), "=r"((r)[3])     \
                 : "r"(addr))

#define LDSM4T(r, addr)                                                       \
    asm volatile("ldmatrix.sync.aligned.m8n8.x4.trans.shared.b16 {%0,%1,%2,%3}, [%4];" \
                 : "=r"((r)[0]), "=r"((r)[1]), "=r"((r)[2]), "=r"((r)[3])     \
                 : "r"(addr))

#define MMA16816(d, a, b0, b1)                                                \
    asm volatile("mma.sync.aligned.m16n8k16.row.col.f32.bf16.bf16.f32 "       \
                 "{%0,%1,%2,%3},{%4,%5,%6,%7},{%8,%9},{%0,%1,%2,%3};"         \
                 : "+f"((d)[0]), "+f"((d)[1]), "+f"((d)[2]), "+f"((d)[3])     \
                 : "r"((a)[0]), "r"((a)[1]), "r"((a)[2]), "r"((a)[3]),        \
                   "r"(b0), "r"(b1))

static __device__ __forceinline__ void cvt_hilo(float x, float y, u32& h, u32& l) {
    __nv_bfloat162 hb = __float22bfloat162_rn(make_float2(x, y));
    float2 hf = __bfloat1622float2(hb);
    __nv_bfloat162 lb = __float22bfloat162_rn(make_float2(x - hf.x, y - hf.y));
    h = *(u32*)&hb;
    l = *(u32*)&lb;
}

__global__ __launch_bounds__(256)
void cvt_split_k(const float4* __restrict__ src, uint2* __restrict__ h,
                 uint2* __restrict__ l, int n4)
{
    int i = blockIdx.x * 256 + threadIdx.x;
    if (i < n4) {
        float4 v = src[i];
        u32 h0, l0, h1, l1;
        cvt_hilo(v.x, v.y, h0, l0);
        cvt_hilo(v.z, v.w, h1, l1);
        h[i] = make_uint2(h0, h1);
        l[i] = make_uint2(l0, l1);
    }
}

// C[row0:+128, n0:+128] = A[rows,:K] @ W[e,:K,n0:+128], bf16 hi/lo plane operands.
// EPI=0: fp32 C.  EPI=1: hi/lo bf16 planes Ch/Cl.
template <int EPI>
__global__ __launch_bounds__(256, 2)
void gemm_moe_async(const __nv_bfloat16* __restrict__ Ah, const __nv_bfloat16* __restrict__ Al,
                    const __nv_bfloat16* __restrict__ Wh, const __nv_bfloat16* __restrict__ Wl,
                    const int* __restrict__ bsz, float* __restrict__ C,
                    __nv_bfloat16* __restrict__ Ch, __nv_bfloat16* __restrict__ Cl,
                    int K, int N)
{
    extern __shared__ __nv_bfloat16 sm[];
    const u32 sbase = smem_u32(sm);
    const int tid = threadIdx.x;
    const int lane = tid & 31;
    const int wid = tid >> 5;
    const int warp_m = wid & 3;
    const int warp_n = wid >> 2;
    const int row0 = blockIdx.y * 128;
    const int n0 = blockIdx.x * 128;

    int cum = 0, e = 0;
#pragma unroll
    for (int i = 0; i < NE; i++) { if (row0 >= cum) e = i; cum += bsz[i]; }
    const size_t woff = (size_t)e * (size_t)K * (size_t)N;

    // ---- cp.async mapping (per thread, per plane): A 2 chunks, B 2 chunks ----
    // A plane: 128 rows x 32 halves (64B = 4 chunks/row). f = tid + i*256, i<2.
    // B plane: 32 rows x 128 halves (256B = 16 chunks/row).
    const int ar = tid >> 2, ac = tid & 3;             // + i*64 rows
    const int bk = tid >> 4, bc = tid & 15;            // + i*16 rows
    const u32 dA0 = (u32)((ar * A_ROW + ac * 8) * 2);
    const u32 dA1 = (u32)(((ar + 64) * A_ROW + ac * 8) * 2);
    const u32 dB0 = (u32)((bk * B_ROW + bc * 8) * 2);
    const u32 dB1 = (u32)(((bk + 16) * B_ROW + bc * 8) * 2);
    const __nv_bfloat16* pAh = Ah + (size_t)(row0 + ar) * K + ac * 8;
    const __nv_bfloat16* pAl = Al + (size_t)(row0 + ar) * K + ac * 8;
    const __nv_bfloat16* pBh = Wh + woff + (size_t)bk * N + n0 + bc * 8;
    const __nv_bfloat16* pBl = Wl + woff + (size_t)bk * N + n0 + bc * 8;
    const size_t aRow64 = (size_t)64 * K;
    const size_t bRow16 = (size_t)16 * N;

    // ---- ldmatrix lane offsets (stage-relative bytes) ----
    const int a_r = lane & 15, a_c = (lane >> 4) * 8;
    u32 aoff[2];
#pragma unroll
    for (int mf = 0; mf < 2; mf++)
        aoff[mf] = (u32)(((warp_m * 32 + mf * 16 + a_r) * A_ROW + a_c) * 2);
    const int b_k = (lane & 7) + 8 * ((lane >> 3) & 1);
    const int b_n = 8 * (lane >> 4);
    u32 boff[4];
#pragma unroll
    for (int j = 0; j < 4; j++)
        boff[j] = (u32)((OFF_BHI + b_k * B_ROW + warp_n * 64 + j * 16 + b_n) * 2);

    float acc[2][8][4];
#pragma unroll
    for (int mf = 0; mf < 2; mf++)
#pragma unroll
        for (int nf = 0; nf < 8; nf++)
#pragma unroll
            for (int v = 0; v < 4; v++) acc[mf][nf][v] = 0.0f;

    const int NS = K >> 5;   // 32 fp32-k per stage

    // ---- prologue: stages 0,1 ----
#pragma unroll
    for (int p = 0; p < NSTAGE - 1; p++) {
        const int kt = p << 5;
        const u32 st = sbase + (u32)(p * STAGE_B);
        CP16(st + dA0, pAh + kt);             CP16(st + dA1, pAh + kt + aRow64);
        CP16(st + OFF_ALO * 2 + dA0, pAl + kt); CP16(st + OFF_ALO * 2 + dA1, pAl + kt + aRow64);
        CP16(st + OFF_BHI * 2 + dB0, pBh + (size_t)kt * N);
        CP16(st + OFF_BHI * 2 + dB1, pBh + (size_t)kt * N + bRow16);
        CP16(st + OFF_BLO * 2 + dB0, pBl + (size_t)kt * N);
        CP16(st + OFF_BLO * 2 + dB1, pBl + (size_t)kt * N + bRow16);
        CP_COMMIT();
    }

    int sidx = 0;  // s % 3
    for (int s = 0; s < NS; s++) {
        CP_WAIT1();
        __syncthreads();

        if (s + 2 < NS) {
            const int kt = (s + 2) << 5;
            int pidx = sidx + 2; if (pidx >= 3) pidx -= 3;
            const u32 st = sbase + (u32)(pidx * STAGE_B);
            CP16(st + dA0, pAh + kt);             CP16(st + dA1, pAh + kt + aRow64);
            CP16(st + OFF_ALO * 2 + dA0, pAl + kt); CP16(st + OFF_ALO * 2 + dA1, pAl + kt + aRow64);
            CP16(st + OFF_BHI * 2 + dB0, pBh + (size_t)kt * N);
            CP16(st + OFF_BHI * 2 + dB1, pBh + (size_t)kt * N + bRow16);
            CP16(st + OFF_BLO * 2 + dB0, pBl + (size_t)kt * N);
            CP16(st + OFF_BLO * 2 + dB1, pBl + (size_t)kt * N + bRow16);
        }
        CP_COMMIT();

        const u32 stb = sbase + (u32)(sidx * STAGE_B);
        sidx++; if (sidx >= 3) sidx -= 3;

#pragma unroll
        for (int ki = 0; ki < 2; ki++) {
            const u32 ka = (u32)(ki * 16 * 2);           // +16 halves along k (A)
            const u32 kb = (u32)(ki * 16 * B_ROW * 2);   // +16 rows (B)
            u32 ah[2][4], al[2][4], bf[4][4];
#pragma unroll
            for (int mf = 0; mf < 2; mf++) LDSM4(ah[mf], stb + aoff[mf] + ka);
#pragma unroll
            for (int mf = 0; mf < 2; mf++) LDSM4(al[mf], stb + aoff[mf] + ka + (u32)(OFF_ALO * 2));
#pragma unroll
            for (int j = 0; j < 4; j++) LDSM4T(bf[j], stb + boff[j] + kb);   // B hi
#pragma unroll
            for (int mf = 0; mf < 2; mf++)
#pragma unroll
                for (int j = 0; j < 4; j++) {
                    MMA16816(acc[mf][2 * j],     ah[mf], bf[j][0], bf[j][1]);
                    MMA16816(acc[mf][2 * j + 1], ah[mf], bf[j][2], bf[j][3]);
                }
#pragma unroll
            for (int mf = 0; mf < 2; mf++)
#pragma unroll
                for (int j = 0; j < 4; j++) {
                    MMA16816(acc[mf][2 * j],     al[mf], bf[j][0], bf[j][1]);
                    MMA16816(acc[mf][2 * j + 1], al[mf], bf[j][2], bf[j][3]);
                }
#pragma unroll
            for (int j = 0; j < 4; j++) LDSM4T(bf[j], stb + boff[j] + kb + (u32)((OFF_BLO - OFF_BHI) * 2));
#pragma unroll
            for (int mf = 0; mf < 2; mf++)
#pragma unroll
                for (int j = 0; j < 4; j++) {
                    MMA16816(acc[mf][2 * j],     ah[mf], bf[j][0], bf[j][1]);
                    MMA16816(acc[mf][2 * j + 1], ah[mf], bf[j][2], bf[j][3]);
                }
        }
    }

    // ---- epilogue ----
#pragma unroll
    for (int mf = 0; mf < 2; mf++)
#pragma unroll
        for (int nf = 0; nf < 8; nf++) {
            int r = row0 + warp_m * 32 + mf * 16 + (lane >> 2);
            int c = n0 + warp_n * 64 + nf * 8 + (lane & 3) * 2;
            if (EPI == 0) {
                *(float2*)(C + (size_t)r * N + c) =
                    make_float2(acc[mf][nf][0], acc[mf][nf][1]);
                *(float2*)(C + (size_t)(r + 8) * N + c) =
                    make_float2(acc[mf][nf][2], acc[mf][nf][3]);
            } else {
                u32 h, l;
                cvt_hilo(acc[mf][nf][0], acc[mf][nf][1], h, l);
                *(u32*)(Ch + (size_t)r * N + c) = h;
                *(u32*)(Cl + (size_t)r * N + c) = l;
                cvt_hilo(acc[mf][nf][2], acc[mf][nf][3], h, l);
                *(u32*)(Ch + (size_t)(r + 8) * N + c) = h;
                *(u32*)(Cl + (size_t)(r + 8) * N + c) = l;
            }
        }
}

extern "C" void kernel_launch(void* const* d_in, const int* in_sizes, int n_in,
                              void* d_out, int out_size)
{
    const float* hiddens = (const float*)d_in[0];
    const int*   bsz     = (const int*)d_in[1];
    const float* w1      = (const float*)d_in[2];
    const float* w2      = (const float*)d_in[3];
    float*       out     = (float*)d_out;

    __nv_bfloat16 *xh, *xl, *w1h, *w1l, *w2h, *w2l, *uph, *upl;
    cudaGetSymbolAddress((void**)&xh, g_xh);   cudaGetSymbolAddress((void**)&xl, g_xl);
    cudaGetSymbolAddress((void**)&w1h, g_w1h); cudaGetSymbolAddress((void**)&w1l, g_w1l);
    cudaGetSymbolAddress((void**)&w2h, g_w2h); cudaGetSymbolAddress((void**)&w2l, g_w2l);
    cudaGetSymbolAddress((void**)&uph, g_uph); cudaGetSymbolAddress((void**)&upl, g_upl);

    cudaFuncSetAttribute(gemm_moe_async<0>, cudaFuncAttributeMaxDynamicSharedMemorySize, SMEM_BYTES);
    cudaFuncSetAttribute(gemm_moe_async<1>, cudaFuncAttributeMaxDynamicSharedMemorySize, SMEM_BYTES);

    {
        int n4 = (TT * HH) / 4;
        cvt_split_k<<<(n4 + 255) / 256, 256>>>((const float4*)hiddens, (uint2*)xh, (uint2*)xl, n4);
    }
    {
        int n4 = (NE * HH * II) / 4;
        cvt_split_k<<<(n4 + 255) / 256, 256>>>((const float4*)w1, (uint2*)w1h, (uint2*)w1l, n4);
        cvt_split_k<<<(n4 + 255) / 256, 256>>>((const float4*)w2, (uint2*)w2h, (uint2*)w2l, n4);
    }

    // up = hiddens @ w1[e] : K=1024, N=4096 ; hi/lo plane output
    gemm_moe_async<1><<<dim3(II / 128, TT / 128), 256, SMEM_BYTES>>>(
        xh, xl, w1h, w1l, bsz, nullptr, uph, upl, HH, II);
    // down = up @ w2[e] : K=4096, N=1024 ; fp32 output
    gemm_moe_async<0><<<dim3(HH / 128, TT / 128), 256, SMEM_BYTES>>>(
        uph, upl, w2h, w2l, bsz, out, nullptr, nullptr, II, HH);
}